// round 4
// baseline (speedup 1.0000x reference)
#include <cuda_runtime.h>
#include <stdint.h>

// Shapes:
//   core0: (1, 50, 8, 16)   -> A[v0][e0][r1]   (A tile per v0 = 128 floats)
//   core1: (16, 50, 4, 16)  -> B[r1][v1][e1][r2]
//   core2: (16, 80, 4, 1)   -> C[r2][v2][e2]
//   indices: 8192, vocab 200000 = (50,50,80) row-major
//   out: (8192, 128) fp32, embed index = e0*16 + e1*4 + e2

#define NV0 50
#define NV1 50
#define NV2 80
#define RANK 16
#define NIDX 8192

// H[(v1*80+v2)][r1][e1*4+e2]: 4000 * 256 floats = 4 MB (L2-resident)
__device__ float g_H[NV1 * NV2 * RANK * 16];

// ---------------------------------------------------------------------------
// Kernel 1: warp per (v1,v2) pair.
//   H[r1][e1*4+e2] = sum_r2 B[r1,v1,e1,r2] * C[r2,v2,e2]
// ---------------------------------------------------------------------------
__global__ __launch_bounds__(256) void tt_build_H(
    const float* __restrict__ core1,   // (16,50,4,16)
    const float* __restrict__ core2)   // (16,80,4,1)
{
    __shared__ __align__(16) float sc[8][64];   // per-warp C slice [r2*4+e2]

    const int w    = threadIdx.x >> 5;
    const int lane = threadIdx.x & 31;
    const int pair = blockIdx.x * 8 + w;        // 0..3999, grid exact
    const int v1   = pair / NV2;
    const int v2   = pair - v1 * NV2;

    if (lane < RANK) {
        const float4 c = __ldg((const float4*)(core2 + ((size_t)lane * NV2 + v2) * 4));
        *(float4*)&sc[w][lane * 4] = c;
    }
    __syncwarp();

    float* hout = g_H + (size_t)pair * (RANK * 16);

#pragma unroll
    for (int pass = 0; pass < 2; ++pass) {
        const int j  = lane + 32 * pass;        // H row id 0..63 (float4 units)
        const int r1 = j >> 2;
        const int e1 = j & 3;

        const float4* B4 = (const float4*)(core1 + (((size_t)r1 * NV1 + v1) * 4 + e1) * RANK);
        const float4 b0 = __ldg(&B4[0]);
        const float4 b1 = __ldg(&B4[1]);
        const float4 b2 = __ldg(&B4[2]);
        const float4 b3 = __ldg(&B4[3]);
        const float bb[RANK] = { b0.x, b0.y, b0.z, b0.w,  b1.x, b1.y, b1.z, b1.w,
                                 b2.x, b2.y, b2.z, b2.w,  b3.x, b3.y, b3.z, b3.w };

        float4 acc = make_float4(0.f, 0.f, 0.f, 0.f);
#pragma unroll
        for (int r2 = 0; r2 < RANK; ++r2) {
            const float4 c4 = *(const float4*)&sc[w][r2 * 4];
            acc.x = fmaf(bb[r2], c4.x, acc.x);
            acc.y = fmaf(bb[r2], c4.y, acc.y);
            acc.z = fmaf(bb[r2], c4.z, acc.z);
            acc.w = fmaf(bb[r2], c4.w, acc.w);
        }
        ((float4*)hout)[j] = acc;               // coalesced STG.128
    }
}

// ---------------------------------------------------------------------------
// Kernel 2: warp per index, cooperative tile staging.
//   Stage A tile (32 float4) + H tile (64 float4) into smem with 3 dedup'd
//   coalesced LDG.128/lane, then compute from LDS broadcast.
//   Lane l: e0=l>>2, q=l&3 owns out[l*4 .. l*4+3].
// ---------------------------------------------------------------------------
__global__ __launch_bounds__(256) void tt_gather(
    const void* __restrict__ idx_raw,
    const float* __restrict__ core0,   // (1,50,8,16)
    float* __restrict__ out)           // (8192,128)
{
    // Per-warp: [0..31] = A tile, [32..95] = H tile (float4 units)
    __shared__ __align__(16) float4 sh[8][96];

    const int w    = threadIdx.x >> 5;
    const int lane = threadIdx.x & 31;
    const int warp = blockIdx.x * 8 + w;

    // dtype sniff: int64 vs int32 (all values < 2e5 -> high words all zero)
    const int* i32 = (const int*)idx_raw;
    const int hw = i32[2 * lane + 1];
    const bool is64 = __all_sync(0xffffffffu, hw == 0);

    int iv;
    if (is64) iv = (int)((const long long*)idx_raw)[warp];
    else      iv = i32[warp];

    const int v0  = iv / (NV1 * NV2);
    const int rem = iv - v0 * (NV1 * NV2);
    const int v1  = rem / NV2;
    const int v2  = rem - v1 * NV2;

    // 3 independent, dedup'd, coalesced tile loads.
    const float4* At = (const float4*)(core0 + (size_t)v0 * 128);            // 32 float4
    const float4* Ht = (const float4*)(g_H + ((size_t)(v1 * NV2 + v2)) * 256); // 64 float4
    const float4 av = __ldg(&At[lane]);
    const float4 h0 = __ldg(&Ht[lane]);
    const float4 h1 = __ldg(&Ht[lane + 32]);
    sh[w][lane]      = av;
    sh[w][32 + lane] = h0;
    sh[w][64 + lane] = h1;
    __syncwarp();

    const int e0 = lane >> 2;
    const int q  = lane & 3;

    // A row e0: 4 LDS.128, 4-lane broadcast each (conflict-free).
    float a[RANK];
#pragma unroll
    for (int k = 0; k < 4; ++k) {
        const float4 t = sh[w][e0 * 4 + k];
        a[4 * k + 0] = t.x; a[4 * k + 1] = t.y; a[4 * k + 2] = t.z; a[4 * k + 3] = t.w;
    }

    // H column quarter q: 16 LDS.128, 8-lane broadcast each (conflict-free).
    float4 acc = make_float4(0.f, 0.f, 0.f, 0.f);
#pragma unroll
    for (int r1 = 0; r1 < RANK; ++r1) {
        const float4 h = sh[w][32 + r1 * 4 + q];
        acc.x = fmaf(a[r1], h.x, acc.x);
        acc.y = fmaf(a[r1], h.y, acc.y);
        acc.z = fmaf(a[r1], h.z, acc.z);
        acc.w = fmaf(a[r1], h.w, acc.w);
    }

    ((float4*)(out + (size_t)warp * 128))[lane] = acc;
}

// Inputs (metadata order): indices, core0, core1, core2
extern "C" void kernel_launch(void* const* d_in, const int* in_sizes, int n_in,
                              void* d_out, int out_size)
{
    const void*  indices = d_in[0];
    const float* core0   = (const float*)d_in[1];
    const float* core1   = (const float*)d_in[2];
    const float* core2   = (const float*)d_in[3];
    float* out = (float*)d_out;

    tt_build_H<<<(NV1 * NV2) / 8, 256>>>(core1, core2);
    tt_gather<<<(NIDX * 32) / 256, 256>>>(indices, core0, out);
}